// round 2
// baseline (speedup 1.0000x reference)
#include <cuda_runtime.h>
#include <math.h>

// Problem constants
#define BB   8
#define CC   256
#define LL   1024          // H*W
#define DIN  512           // d_inner
#define DST  16            // d_state
#define RANK 16
#define HID  1024
#define MM   (BB*LL)       // 8192 tokens

// ---------------- scratch (device globals; no allocation APIs) -------------
__device__ float g_xt [MM*CC];     // x transposed (B,L,C) == residual 1
__device__ float g_xn [MM*CC];     // LN1 out
__device__ float g_xz [MM*2*DIN];  // xn @ W_in
__device__ float g_xm [MM*DIN];    // conv+silu out
__device__ float g_dbl[MM*48];     // xm @ W_x  (dt_raw | B | C)
__device__ float g_dt [MM*DIN];    // softplus(dt_raw @ W_dt + b_dt)
__device__ float g_y  [MM*DIN];    // scan output
__device__ float g_yg [MM*DIN];    // gated y
__device__ float g_x2 [MM*CC];     // mamba out + res (residual 2)
__device__ float g_xn2[MM*CC];     // LN2 out
__device__ float g_h1 [MM*HID];    // gelu(xn2@W1+b1)
__device__ float g_x3 [MM*CC];     // final (B,L,C) before transpose

// ---------------- batched 2D transpose: (b,R,C) -> (b,C,R) -----------------
__global__ void transpose_k(const float* __restrict__ in, float* __restrict__ out,
                            int R, int Cc) {
    __shared__ float t[32][33];
    int b  = blockIdx.z;
    int r0 = blockIdx.y * 32, c0 = blockIdx.x * 32;
    const float* ib = in  + (size_t)b * R * Cc;
    float*       ob = out + (size_t)b * R * Cc;
#pragma unroll
    for (int i = 0; i < 32; i += 8)
        t[threadIdx.y + i][threadIdx.x] = ib[(r0 + threadIdx.y + i) * Cc + c0 + threadIdx.x];
    __syncthreads();
#pragma unroll
    for (int i = 0; i < 32; i += 8)
        ob[(c0 + threadIdx.y + i) * R + r0 + threadIdx.x] = t[threadIdx.x][threadIdx.y + i];
}

// ---------------- layernorm over C=256, one block per token ----------------
__global__ void layernorm_k(const float* __restrict__ in, float* __restrict__ out,
                            const float* __restrict__ g, const float* __restrict__ bt) {
    int row = blockIdx.x;
    int tid = threadIdx.x;          // 256
    float v = in[row * CC + tid];
    float s = v, sq = v * v;
#pragma unroll
    for (int o = 16; o; o >>= 1) {
        s  += __shfl_xor_sync(0xffffffffu, s,  o);
        sq += __shfl_xor_sync(0xffffffffu, sq, o);
    }
    __shared__ float ss[8], ssq[8];
    int w = tid >> 5;
    if ((tid & 31) == 0) { ss[w] = s; ssq[w] = sq; }
    __syncthreads();
    float tot = 0.f, totq = 0.f;
#pragma unroll
    for (int i = 0; i < 8; i++) { tot += ss[i]; totq += ssq[i]; }
    float mu  = tot * (1.0f / CC);
    float var = totq * (1.0f / CC) - mu * mu;
    out[row * CC + tid] = (v - mu) * rsqrtf(var + 1e-5f) * g[tid] + bt[tid];
}

// ---------------- generic SGEMM: C = A(MxK) @ B(KxN) (+epilogue) -----------
// EPI: 0 none, 1 +res, 2 +bias & gelu, 3 +bias +res
template<int EPI>
__global__ void sgemm_k(const float* __restrict__ A, const float* __restrict__ B,
                        float* __restrict__ Cout, int M, int N, int K,
                        const float* __restrict__ bias, const float* __restrict__ res) {
    __shared__ float As[8][128];
    __shared__ float Bs[8][128];
    int tid = threadIdx.x;
    int bm = blockIdx.y * 128, bn = blockIdx.x * 128;
    int tx = tid & 15, ty = tid >> 4;        // 16x16 threads, each 8x8
    int aRow = tid >> 1;                      // 0..127
    int aCol = (tid & 1) << 2;                // 0 or 4
    int bRow = tid >> 5;                      // 0..7
    int bCol = (tid & 31) << 2;               // 0..124

    float acc[8][8];
#pragma unroll
    for (int i = 0; i < 8; i++)
#pragma unroll
        for (int j = 0; j < 8; j++) acc[i][j] = 0.f;

    for (int k0 = 0; k0 < K; k0 += 8) {
        float4 av = *(const float4*)(A + (size_t)(bm + aRow) * K + k0 + aCol);
        As[aCol + 0][aRow] = av.x;
        As[aCol + 1][aRow] = av.y;
        As[aCol + 2][aRow] = av.z;
        As[aCol + 3][aRow] = av.w;
        *(float4*)(&Bs[bRow][bCol]) = *(const float4*)(B + (size_t)(k0 + bRow) * N + bn + bCol);
        __syncthreads();
#pragma unroll
        for (int kk = 0; kk < 8; kk++) {
            float4 a0 = *(float4*)(&As[kk][ty * 8]);
            float4 a1 = *(float4*)(&As[kk][ty * 8 + 4]);
            float4 b0 = *(float4*)(&Bs[kk][tx * 8]);
            float4 b1 = *(float4*)(&Bs[kk][tx * 8 + 4]);
            float ra[8] = {a0.x, a0.y, a0.z, a0.w, a1.x, a1.y, a1.z, a1.w};
            float rb[8] = {b0.x, b0.y, b0.z, b0.w, b1.x, b1.y, b1.z, b1.w};
#pragma unroll
            for (int i = 0; i < 8; i++)
#pragma unroll
                for (int j = 0; j < 8; j++)
                    acc[i][j] = fmaf(ra[i], rb[j], acc[i][j]);
        }
        __syncthreads();
    }

#pragma unroll
    for (int i = 0; i < 8; i++) {
        int row = bm + ty * 8 + i;
#pragma unroll
        for (int j = 0; j < 8; j++) {
            int col = bn + tx * 8 + j;
            float v = acc[i][j];
            if (EPI == 1) v += res[(size_t)row * N + col];
            if (EPI == 2) {
                v += bias[col];
                v = 0.5f * v * (1.0f + erff(v * 0.70710678118654752f));
            }
            if (EPI == 3) v += bias[col] + res[(size_t)row * N + col];
            Cout[(size_t)row * N + col] = v;
        }
    }
}

// ---------------- depthwise causal conv1d (d_conv=4) + silu ----------------
__global__ void conv_silu_k(const float* __restrict__ xz, const float* __restrict__ cw,
                            const float* __restrict__ cb, float* __restrict__ xm) {
    int idx = blockIdx.x * blockDim.x + threadIdx.x;   // MM*DIN
    if (idx >= MM * DIN) return;
    int d = idx & (DIN - 1);
    int t = idx >> 9;            // token index b*L + l
    int l = t & (LL - 1);
    int b = t >> 10;
    float acc = cb[d];
#pragma unroll
    for (int k = 0; k < 4; k++) {
        int ls = l + k - 3;
        if (ls >= 0)
            acc = fmaf(xz[((size_t)((b << 10) + ls)) * (2 * DIN) + d], cw[d * 4 + k], acc);
    }
    float sg = 1.0f / (1.0f + __expf(-acc));
    xm[idx] = acc * sg;
}

// ---------------- small GEMM: dbl = xm(8192x512) @ W_x(512x48) -------------
__global__ void gemm_wx_k(const float* __restrict__ xm, const float* __restrict__ Wx,
                          float* __restrict__ dbl) {
    __shared__ float As[32][17];
    __shared__ float Ws[16][48];
    int m0  = blockIdx.x * 32;
    int tid = threadIdx.x;           // 256
    int row = tid >> 3;              // 0..31
    int cg  = tid & 7;               // col group, 6 cols each
    float acc[6] = {0.f, 0.f, 0.f, 0.f, 0.f, 0.f};
    for (int kc = 0; kc < DIN; kc += 16) {
        int e = tid * 2;
        As[e >> 4][e & 15]       = xm[(size_t)(m0 + (e >> 4)) * DIN + kc + (e & 15)];
        e++;
        As[e >> 4][e & 15]       = xm[(size_t)(m0 + (e >> 4)) * DIN + kc + (e & 15)];
        int f = tid * 3;
#pragma unroll
        for (int q = 0; q < 3; q++, f++)
            Ws[f / 48][f % 48] = Wx[(size_t)(kc + f / 48) * 48 + (f % 48)];
        __syncthreads();
#pragma unroll
        for (int kk = 0; kk < 16; kk++) {
            float a = As[row][kk];
#pragma unroll
            for (int j = 0; j < 6; j++)
                acc[j] = fmaf(a, Ws[kk][cg * 6 + j], acc[j]);
        }
        __syncthreads();
    }
#pragma unroll
    for (int j = 0; j < 6; j++)
        dbl[(size_t)(m0 + row) * 48 + cg * 6 + j] = acc[j];
}

// ---------------- dt = softplus(dbl[:, :16] @ W_dt + b_dt) -----------------
__global__ void dt_softplus_k(const float* __restrict__ dbl, const float* __restrict__ Wdt,
                              const float* __restrict__ bdt, float* __restrict__ dt) {
    int m = blockIdx.x;
    int tid = threadIdx.x;           // 256
    __shared__ float r[16];
    if (tid < 16) r[tid] = dbl[(size_t)m * 48 + tid];
    __syncthreads();
#pragma unroll
    for (int n = tid; n < DIN; n += 256) {
        float acc = bdt[n];
#pragma unroll
        for (int k = 0; k < 16; k++)
            acc = fmaf(r[k], Wdt[(size_t)k * DIN + n], acc);
        float sp = (acc > 20.f) ? acc : log1pf(__expf(acc));
        dt[(size_t)m * DIN + n] = sp;
    }
}

// ---------------- selective scan: half-warp per channel --------------------
// lane s = lane&15 holds state s; lanes 0-15 -> channel d0, 16-31 -> d1.
__global__ void scan_k(const float* __restrict__ dt, const float* __restrict__ xm,
                       const float* __restrict__ dbl, const float* __restrict__ Alog,
                       float* __restrict__ y) {
    int warpId = threadIdx.x >> 5;
    int lane   = threadIdx.x & 31;
    int gw     = blockIdx.x * (blockDim.x >> 5) + warpId;   // 0..2047
    int b      = gw >> 8;                                   // 256 pairs per batch
    int pair   = gw & 255;
    int ch     = lane >> 4;
    int s      = lane & 15;
    int d      = pair * 2 + ch;

    float a = -__expf(Alog[d * DST + s]);
    float h = 0.f;
    int tb = b << 10;
    for (int l = 0; l < LL; l++) {
        int t = tb + l;
        float dtv = dt[(size_t)t * DIN + d];
        float xv  = xm[(size_t)t * DIN + d];
        float Bv  = dbl[(size_t)t * 48 + 16 + s];
        float Cv  = dbl[(size_t)t * 48 + 32 + s];
        float dA  = __expf(dtv * a);
        h = fmaf(dA, h, dtv * xv * Bv);
        float p = h * Cv;
        p += __shfl_xor_sync(0xffffffffu, p, 8);
        p += __shfl_xor_sync(0xffffffffu, p, 4);
        p += __shfl_xor_sync(0xffffffffu, p, 2);
        p += __shfl_xor_sync(0xffffffffu, p, 1);
        if (s == 0) y[(size_t)t * DIN + d] = p;
    }
}

// ---------------- gate: yg = (y + xm*D) * silu(z) --------------------------
__global__ void gate_k(const float* __restrict__ xz, const float* __restrict__ y,
                       const float* __restrict__ xm, const float* __restrict__ Dp,
                       float* __restrict__ yg) {
    int idx = blockIdx.x * blockDim.x + threadIdx.x;
    if (idx >= MM * DIN) return;
    int d = idx & (DIN - 1);
    int t = idx >> 9;
    float z  = xz[(size_t)t * (2 * DIN) + DIN + d];
    float sz = z / (1.0f + __expf(-z));
    yg[idx] = fmaf(xm[idx], Dp[d], y[idx]) * sz;
}

// ---------------------------- launch ---------------------------------------
extern "C" void kernel_launch(void* const* d_in, const int* in_sizes, int n_in,
                              void* d_out, int out_size) {
    const float* x      = (const float*)d_in[0];
    const float* ln1_g  = (const float*)d_in[1];
    const float* ln1_b  = (const float*)d_in[2];
    const float* ln2_g  = (const float*)d_in[3];
    const float* ln2_b  = (const float*)d_in[4];
    const float* W_in   = (const float*)d_in[5];
    const float* conv_w = (const float*)d_in[6];
    const float* conv_b = (const float*)d_in[7];
    const float* W_x    = (const float*)d_in[8];
    const float* W_dt   = (const float*)d_in[9];
    const float* b_dt   = (const float*)d_in[10];
    const float* A_log  = (const float*)d_in[11];
    const float* D_par  = (const float*)d_in[12];
    const float* W_out  = (const float*)d_in[13];
    const float* W1     = (const float*)d_in[14];
    const float* b1     = (const float*)d_in[15];
    const float* W2     = (const float*)d_in[16];
    const float* b2     = (const float*)d_in[17];
    float* out = (float*)d_out;

    float *xt, *xn, *xz, *xm, *dbl, *dtp, *y, *yg, *x2, *xn2, *h1, *x3;
    cudaGetSymbolAddress((void**)&xt,  g_xt);
    cudaGetSymbolAddress((void**)&xn,  g_xn);
    cudaGetSymbolAddress((void**)&xz,  g_xz);
    cudaGetSymbolAddress((void**)&xm,  g_xm);
    cudaGetSymbolAddress((void**)&dbl, g_dbl);
    cudaGetSymbolAddress((void**)&dtp, g_dt);
    cudaGetSymbolAddress((void**)&y,   g_y);
    cudaGetSymbolAddress((void**)&yg,  g_yg);
    cudaGetSymbolAddress((void**)&x2,  g_x2);
    cudaGetSymbolAddress((void**)&xn2, g_xn2);
    cudaGetSymbolAddress((void**)&h1,  g_h1);
    cudaGetSymbolAddress((void**)&x3,  g_x3);

    dim3 tb(32, 8);

    // 1) transpose (B,C,L) -> (B,L,C)
    transpose_k<<<dim3(LL / 32, CC / 32, BB), tb>>>(x, xt, CC, LL);
    // 2) LN1
    layernorm_k<<<MM, 256>>>(xt, xn, ln1_g, ln1_b);
    // 3) xz = xn @ W_in
    sgemm_k<0><<<dim3((2 * DIN) / 128, MM / 128), 256>>>(xn, W_in, xz, MM, 2 * DIN, CC, nullptr, nullptr);
    // 4) depthwise causal conv + silu
    conv_silu_k<<<(MM * DIN) / 256, 256>>>(xz, conv_w, conv_b, xm);
    // 5) dbl = xm @ W_x
    gemm_wx_k<<<MM / 32, 256>>>(xm, W_x, dbl);
    // 6) dt = softplus(dbl[:, :16] @ W_dt + b_dt)
    dt_softplus_k<<<MM, 256>>>(dbl, W_dt, b_dt, dtp);
    // 7) selective scan
    scan_k<<<(BB * (DIN / 2)) / 8, 256>>>(dtp, xm, dbl, A_log, y);
    // 8) gate
    gate_k<<<(MM * DIN) / 256, 256>>>(xz, y, xm, D_par, yg);
    // 9) x2 = yg @ W_out + res
    sgemm_k<1><<<dim3(CC / 128, MM / 128), 256>>>(yg, W_out, x2, MM, CC, DIN, nullptr, xt);
    // 10) LN2
    layernorm_k<<<MM, 256>>>(x2, xn2, ln2_g, ln2_b);
    // 11) h1 = gelu(xn2 @ W1 + b1)
    sgemm_k<2><<<dim3(HID / 128, MM / 128), 256>>>(xn2, W1, h1, MM, HID, CC, b1, nullptr);
    // 12) x3 = h1 @ W2 + b2 + x2
    sgemm_k<3><<<dim3(CC / 128, MM / 128), 256>>>(h1, W2, x3, MM, CC, HID, b2, x2);
    // 13) transpose back (B,L,C) -> (B,C,L)
    transpose_k<<<dim3(CC / 32, LL / 32, BB), tb>>>(x3, out, LL, CC);
}

// round 3
// speedup vs baseline: 1.5416x; 1.5416x over previous
#include <cuda_runtime.h>
#include <math.h>
#include <stdint.h>

// Problem constants
#define BB   8
#define CC   256
#define LL   1024          // H*W
#define DIN  512           // d_inner
#define DST  16            // d_state
#define RANK 16
#define HID  1024
#define MM   (BB*LL)       // 8192 tokens

// ---------------- scratch (device globals; no allocation APIs) -------------
__device__ float g_xt [MM*CC];     // x transposed (B,L,C) == residual 1
__device__ float g_xn [MM*CC];     // LN1 out
__device__ float g_xz [MM*2*DIN];  // xn @ W_in
__device__ float g_xm [MM*DIN];    // conv+silu out
__device__ float g_dbl[MM*48];     // xm @ W_x  (dt_raw | B | C)
__device__ float g_dt [MM*DIN];    // softplus(dt_raw @ W_dt + b_dt)
__device__ float g_y  [MM*DIN];    // scan output
__device__ float g_yg [MM*DIN];    // gated y
__device__ float g_x2 [MM*CC];     // mamba out + res (residual 2)
__device__ float g_xn2[MM*CC];     // LN2 out
__device__ float g_h1 [MM*HID];    // gelu(xn2@W1+b1)
__device__ float g_x3 [MM*CC];     // final (B,L,C) before transpose

// ---------------- batched 2D transpose: (b,R,C) -> (b,C,R) -----------------
__global__ void transpose_k(const float* __restrict__ in, float* __restrict__ out,
                            int R, int Cc) {
    __shared__ float t[32][33];
    int b  = blockIdx.z;
    int r0 = blockIdx.y * 32, c0 = blockIdx.x * 32;
    const float* ib = in  + (size_t)b * R * Cc;
    float*       ob = out + (size_t)b * R * Cc;
#pragma unroll
    for (int i = 0; i < 32; i += 8)
        t[threadIdx.y + i][threadIdx.x] = ib[(r0 + threadIdx.y + i) * Cc + c0 + threadIdx.x];
    __syncthreads();
#pragma unroll
    for (int i = 0; i < 32; i += 8)
        ob[(c0 + threadIdx.y + i) * R + r0 + threadIdx.x] = t[threadIdx.x][threadIdx.y + i];
}

// ---------------- layernorm over C=256, one block per token ----------------
__global__ void layernorm_k(const float* __restrict__ in, float* __restrict__ out,
                            const float* __restrict__ g, const float* __restrict__ bt) {
    int row = blockIdx.x;
    int tid = threadIdx.x;          // 256
    float v = in[row * CC + tid];
    float s = v, sq = v * v;
#pragma unroll
    for (int o = 16; o; o >>= 1) {
        s  += __shfl_xor_sync(0xffffffffu, s,  o);
        sq += __shfl_xor_sync(0xffffffffu, sq, o);
    }
    __shared__ float ss[8], ssq[8];
    int w = tid >> 5;
    if ((tid & 31) == 0) { ss[w] = s; ssq[w] = sq; }
    __syncthreads();
    float tot = 0.f, totq = 0.f;
#pragma unroll
    for (int i = 0; i < 8; i++) { tot += ss[i]; totq += ssq[i]; }
    float mu  = tot * (1.0f / CC);
    float var = totq * (1.0f / CC) - mu * mu;
    out[row * CC + tid] = (v - mu) * rsqrtf(var + 1e-5f) * g[tid] + bt[tid];
}

// ---------------- tf32 tensor-core GEMM ------------------------------------
// C = A(MxK) @ B(KxN) (+epilogue). EPI: 0 none, 1 +res, 2 +bias&gelu, 3 +bias+res
__device__ __forceinline__ uint32_t f2tf32(float x) {
    uint32_t r;
    asm("cvt.rna.tf32.f32 %0, %1;" : "=r"(r) : "f"(x));
    return r;
}

__device__ __forceinline__ void mma_tf32(float* c, const uint32_t* a,
                                         uint32_t b0, uint32_t b1) {
    asm volatile(
        "mma.sync.aligned.m16n8k8.row.col.f32.tf32.tf32.f32 "
        "{%0,%1,%2,%3}, {%4,%5,%6,%7}, {%8,%9}, {%0,%1,%2,%3};"
        : "+f"(c[0]), "+f"(c[1]), "+f"(c[2]), "+f"(c[3])
        : "r"(a[0]), "r"(a[1]), "r"(a[2]), "r"(a[3]), "r"(b0), "r"(b1));
}

template<int EPI>
__global__ __launch_bounds__(256, 2)
void tf32gemm_k(const float* __restrict__ A, const float* __restrict__ Bm,
                float* __restrict__ Cout, int M, int N, int K,
                const float* __restrict__ bias, const float* __restrict__ res) {
    __shared__ uint32_t As[32][132];   // [k][m], padded
    __shared__ uint32_t Bs[32][132];   // [k][n], padded
    int tid  = threadIdx.x;
    int lane = tid & 31, warp = tid >> 5;
    int warpM = warp >> 1, warpN = warp & 1;     // 4 x 2 warps
    int bm = blockIdx.y * 128, bn = blockIdx.x * 128;
    int row4 = lane >> 2, kq = lane & 3;

    float acc[2][8][4];
#pragma unroll
    for (int i = 0; i < 2; i++)
#pragma unroll
        for (int j = 0; j < 8; j++)
#pragma unroll
            for (int q = 0; q < 4; q++) acc[i][j][q] = 0.f;

    for (int k0 = 0; k0 < K; k0 += 32) {
        // load A tile (128 rows x 32 k) -> As[k][m]
#pragma unroll
        for (int q = 0; q < 4; q++) {
            int idx = tid + 256 * q;
            int r = idx >> 3, c = (idx & 7) << 2;
            float4 v = *(const float4*)(A + (size_t)(bm + r) * K + k0 + c);
            As[c + 0][r] = f2tf32(v.x);
            As[c + 1][r] = f2tf32(v.y);
            As[c + 2][r] = f2tf32(v.z);
            As[c + 3][r] = f2tf32(v.w);
        }
        // load B tile (32 k x 128 n) -> Bs[k][n]
#pragma unroll
        for (int q = 0; q < 4; q++) {
            int idx = tid + 256 * q;
            int kk = idx >> 5, n = (idx & 31) << 2;
            float4 v = *(const float4*)(Bm + (size_t)(k0 + kk) * N + bn + n);
            Bs[kk][n + 0] = f2tf32(v.x);
            Bs[kk][n + 1] = f2tf32(v.y);
            Bs[kk][n + 2] = f2tf32(v.z);
            Bs[kk][n + 3] = f2tf32(v.w);
        }
        __syncthreads();
#pragma unroll
        for (int ks = 0; ks < 32; ks += 8) {
            uint32_t af[2][4];
#pragma unroll
            for (int mi = 0; mi < 2; mi++) {
                int m0 = warpM * 32 + mi * 16;
                af[mi][0] = As[ks + kq][m0 + row4];
                af[mi][1] = As[ks + kq][m0 + 8 + row4];
                af[mi][2] = As[ks + 4 + kq][m0 + row4];
                af[mi][3] = As[ks + 4 + kq][m0 + 8 + row4];
            }
#pragma unroll
            for (int ni = 0; ni < 8; ni++) {
                int n0 = warpN * 64 + ni * 8;
                uint32_t b0 = Bs[ks + kq][n0 + row4];
                uint32_t b1 = Bs[ks + 4 + kq][n0 + row4];
                mma_tf32(acc[0][ni], af[0], b0, b1);
                mma_tf32(acc[1][ni], af[1], b0, b1);
            }
        }
        __syncthreads();
    }

    // epilogue
#pragma unroll
    for (int mi = 0; mi < 2; mi++) {
        int r0 = bm + warpM * 32 + mi * 16 + row4;
#pragma unroll
        for (int ni = 0; ni < 8; ni++) {
            int col = bn + warpN * 64 + ni * 8 + kq * 2;
#pragma unroll
            for (int half = 0; half < 2; half++) {
                int row = r0 + half * 8;
                float v0 = acc[mi][ni][half * 2 + 0];
                float v1 = acc[mi][ni][half * 2 + 1];
                if (EPI == 1) {
                    v0 += res[(size_t)row * N + col];
                    v1 += res[(size_t)row * N + col + 1];
                }
                if (EPI == 2) {
                    v0 += bias[col];
                    v1 += bias[col + 1];
                    v0 = 0.5f * v0 * (1.0f + erff(v0 * 0.70710678118654752f));
                    v1 = 0.5f * v1 * (1.0f + erff(v1 * 0.70710678118654752f));
                }
                if (EPI == 3) {
                    v0 += bias[col]     + res[(size_t)row * N + col];
                    v1 += bias[col + 1] + res[(size_t)row * N + col + 1];
                }
                float2 o = make_float2(v0, v1);
                *(float2*)(Cout + (size_t)row * N + col) = o;
            }
        }
    }
}

// ---------------- depthwise causal conv1d (d_conv=4) + silu ----------------
__global__ void conv_silu_k(const float* __restrict__ xz, const float* __restrict__ cw,
                            const float* __restrict__ cb, float* __restrict__ xm) {
    int idx = blockIdx.x * blockDim.x + threadIdx.x;   // MM*DIN
    if (idx >= MM * DIN) return;
    int d = idx & (DIN - 1);
    int t = idx >> 9;            // token index b*L + l
    int l = t & (LL - 1);
    int b = t >> 10;
    float acc = cb[d];
#pragma unroll
    for (int k = 0; k < 4; k++) {
        int ls = l + k - 3;
        if (ls >= 0)
            acc = fmaf(xz[((size_t)((b << 10) + ls)) * (2 * DIN) + d], cw[d * 4 + k], acc);
    }
    float sg = 1.0f / (1.0f + __expf(-acc));
    xm[idx] = acc * sg;
}

// ---------------- small GEMM: dbl = xm(8192x512) @ W_x(512x48) -------------
__global__ void gemm_wx_k(const float* __restrict__ xm, const float* __restrict__ Wx,
                          float* __restrict__ dbl) {
    __shared__ float As[32][17];
    __shared__ float Ws[16][48];
    int m0  = blockIdx.x * 32;
    int tid = threadIdx.x;           // 256
    int row = tid >> 3;              // 0..31
    int cg  = tid & 7;               // col group, 6 cols each
    float acc[6] = {0.f, 0.f, 0.f, 0.f, 0.f, 0.f};
    for (int kc = 0; kc < DIN; kc += 16) {
        int e = tid * 2;
        As[e >> 4][e & 15]       = xm[(size_t)(m0 + (e >> 4)) * DIN + kc + (e & 15)];
        e++;
        As[e >> 4][e & 15]       = xm[(size_t)(m0 + (e >> 4)) * DIN + kc + (e & 15)];
        int f = tid * 3;
#pragma unroll
        for (int q = 0; q < 3; q++, f++)
            Ws[f / 48][f % 48] = Wx[(size_t)(kc + f / 48) * 48 + (f % 48)];
        __syncthreads();
#pragma unroll
        for (int kk = 0; kk < 16; kk++) {
            float a = As[row][kk];
#pragma unroll
            for (int j = 0; j < 6; j++)
                acc[j] = fmaf(a, Ws[kk][cg * 6 + j], acc[j]);
        }
        __syncthreads();
    }
#pragma unroll
    for (int j = 0; j < 6; j++)
        dbl[(size_t)(m0 + row) * 48 + cg * 6 + j] = acc[j];
}

// ---------------- dt = softplus(dbl[:, :16] @ W_dt + b_dt) -----------------
__global__ void dt_softplus_k(const float* __restrict__ dbl, const float* __restrict__ Wdt,
                              const float* __restrict__ bdt, float* __restrict__ dt) {
    int m = blockIdx.x;
    int tid = threadIdx.x;           // 256
    __shared__ float r[16];
    if (tid < 16) r[tid] = dbl[(size_t)m * 48 + tid];
    __syncthreads();
#pragma unroll
    for (int n = tid; n < DIN; n += 256) {
        float acc = bdt[n];
#pragma unroll
        for (int k = 0; k < 16; k++)
            acc = fmaf(r[k], Wdt[(size_t)k * DIN + n], acc);
        float sp = (acc > 20.f) ? acc : log1pf(__expf(acc));
        dt[(size_t)m * DIN + n] = sp;
    }
}

// ---------------- selective scan: half-warp per channel --------------------
__global__ void scan_k(const float* __restrict__ dt, const float* __restrict__ xm,
                       const float* __restrict__ dbl, const float* __restrict__ Alog,
                       float* __restrict__ y) {
    int warpId = threadIdx.x >> 5;
    int lane   = threadIdx.x & 31;
    int gw     = blockIdx.x * (blockDim.x >> 5) + warpId;   // 0..2047
    int b      = gw >> 8;                                   // 256 pairs per batch
    int pair   = gw & 255;
    int ch     = lane >> 4;
    int s      = lane & 15;
    int d      = pair * 2 + ch;

    float a = -__expf(Alog[d * DST + s]);
    float h = 0.f;
    int tb = b << 10;
    for (int l = 0; l < LL; l++) {
        int t = tb + l;
        float dtv = dt[(size_t)t * DIN + d];
        float xv  = xm[(size_t)t * DIN + d];
        float Bv  = dbl[(size_t)t * 48 + 16 + s];
        float Cv  = dbl[(size_t)t * 48 + 32 + s];
        float dA  = __expf(dtv * a);
        h = fmaf(dA, h, dtv * xv * Bv);
        float p = h * Cv;
        p += __shfl_xor_sync(0xffffffffu, p, 8);
        p += __shfl_xor_sync(0xffffffffu, p, 4);
        p += __shfl_xor_sync(0xffffffffu, p, 2);
        p += __shfl_xor_sync(0xffffffffu, p, 1);
        if (s == 0) y[(size_t)t * DIN + d] = p;
    }
}

// ---------------- gate: yg = (y + xm*D) * silu(z) --------------------------
__global__ void gate_k(const float* __restrict__ xz, const float* __restrict__ y,
                       const float* __restrict__ xm, const float* __restrict__ Dp,
                       float* __restrict__ yg) {
    int idx = blockIdx.x * blockDim.x + threadIdx.x;
    if (idx >= MM * DIN) return;
    int d = idx & (DIN - 1);
    int t = idx >> 9;
    float z  = xz[(size_t)t * (2 * DIN) + DIN + d];
    float sz = z / (1.0f + __expf(-z));
    yg[idx] = fmaf(xm[idx], Dp[d], y[idx]) * sz;
}

// ---------------------------- launch ---------------------------------------
extern "C" void kernel_launch(void* const* d_in, const int* in_sizes, int n_in,
                              void* d_out, int out_size) {
    const float* x      = (const float*)d_in[0];
    const float* ln1_g  = (const float*)d_in[1];
    const float* ln1_b  = (const float*)d_in[2];
    const float* ln2_g  = (const float*)d_in[3];
    const float* ln2_b  = (const float*)d_in[4];
    const float* W_in   = (const float*)d_in[5];
    const float* conv_w = (const float*)d_in[6];
    const float* conv_b = (const float*)d_in[7];
    const float* W_x    = (const float*)d_in[8];
    const float* W_dt   = (const float*)d_in[9];
    const float* b_dt   = (const float*)d_in[10];
    const float* A_log  = (const float*)d_in[11];
    const float* D_par  = (const float*)d_in[12];
    const float* W_out  = (const float*)d_in[13];
    const float* W1     = (const float*)d_in[14];
    const float* b1     = (const float*)d_in[15];
    const float* W2     = (const float*)d_in[16];
    const float* b2     = (const float*)d_in[17];
    float* out = (float*)d_out;

    float *xt, *xn, *xz, *xm, *dbl, *dtp, *y, *yg, *x2, *xn2, *h1, *x3;
    cudaGetSymbolAddress((void**)&xt,  g_xt);
    cudaGetSymbolAddress((void**)&xn,  g_xn);
    cudaGetSymbolAddress((void**)&xz,  g_xz);
    cudaGetSymbolAddress((void**)&xm,  g_xm);
    cudaGetSymbolAddress((void**)&dbl, g_dbl);
    cudaGetSymbolAddress((void**)&dtp, g_dt);
    cudaGetSymbolAddress((void**)&y,   g_y);
    cudaGetSymbolAddress((void**)&yg,  g_yg);
    cudaGetSymbolAddress((void**)&x2,  g_x2);
    cudaGetSymbolAddress((void**)&xn2, g_xn2);
    cudaGetSymbolAddress((void**)&h1,  g_h1);
    cudaGetSymbolAddress((void**)&x3,  g_x3);

    dim3 tb(32, 8);

    // 1) transpose (B,C,L) -> (B,L,C)
    transpose_k<<<dim3(LL / 32, CC / 32, BB), tb>>>(x, xt, CC, LL);
    // 2) LN1
    layernorm_k<<<MM, 256>>>(xt, xn, ln1_g, ln1_b);
    // 3) xz = xn @ W_in  (tensor cores, tf32)
    tf32gemm_k<0><<<dim3((2 * DIN) / 128, MM / 128), 256>>>(xn, W_in, xz, MM, 2 * DIN, CC, nullptr, nullptr);
    // 4) depthwise causal conv + silu
    conv_silu_k<<<(MM * DIN) / 256, 256>>>(xz, conv_w, conv_b, xm);
    // 5) dbl = xm @ W_x
    gemm_wx_k<<<MM / 32, 256>>>(xm, W_x, dbl);
    // 6) dt = softplus(dbl[:, :16] @ W_dt + b_dt)
    dt_softplus_k<<<MM, 256>>>(dbl, W_dt, b_dt, dtp);
    // 7) selective scan
    scan_k<<<(BB * (DIN / 2)) / 8, 256>>>(dtp, xm, dbl, A_log, y);
    // 8) gate
    gate_k<<<(MM * DIN) / 256, 256>>>(xz, y, xm, D_par, yg);
    // 9) x2 = yg @ W_out + res  (tensor cores, tf32)
    tf32gemm_k<1><<<dim3(CC / 128, MM / 128), 256>>>(yg, W_out, x2, MM, CC, DIN, nullptr, xt);
    // 10) LN2
    layernorm_k<<<MM, 256>>>(x2, xn2, ln2_g, ln2_b);
    // 11) h1 = gelu(xn2 @ W1 + b1)  (tensor cores, tf32)
    tf32gemm_k<2><<<dim3(HID / 128, MM / 128), 256>>>(xn2, W1, h1, MM, HID, CC, b1, nullptr);
    // 12) x3 = h1 @ W2 + b2 + x2  (tensor cores, tf32)
    tf32gemm_k<3><<<dim3(CC / 128, MM / 128), 256>>>(h1, W2, x3, MM, CC, HID, b2, x2);
    // 13) transpose back (B,L,C) -> (B,C,L)
    transpose_k<<<dim3(CC / 32, LL / 32, BB), tb>>>(x3, out, LL, CC);
}